// round 10
// baseline (speedup 1.0000x reference)
#include <cuda_runtime.h>

#define NMAX 50000
#define EMAX 800000
#define HID 64
#define TE 32   // edges per tile in edge kernel

// ---------- scratch (device globals; no allocation allowed) ----------
__device__ float g_h[NMAX * HID];
__device__ float g_x[NMAX * 3];
__device__ float g_Pa[NMAX * HID];   // h @ W1a + b1  (gathered at row)
__device__ float g_Pb[NMAX * HID];   // h @ W1b       (gathered at col)
__device__ float g_agg[NMAX * HID];  // segment_sum of m
__device__ float g_trans[NMAX * 3];  // segment_sum of diff * s
__device__ float g_cnt[NMAX];

__device__ __forceinline__ float silu_f(float v) {
    return v * (1.0f / (1.0f + __expf(-v)));
}

__device__ __forceinline__ unsigned long long pack2(float lo, float hi) {
    unsigned long long r;
    asm("mov.b64 %0, {%1, %2};" : "=l"(r) : "r"(__float_as_uint(lo)), "r"(__float_as_uint(hi)));
    return r;
}
__device__ __forceinline__ unsigned long long bcast2(float v) {
    unsigned long long r;
    unsigned u = __float_as_uint(v);
    asm("mov.b64 %0, {%1, %1};" : "=l"(r) : "r"(u));
    return r;
}
__device__ __forceinline__ void unpack2(unsigned long long p, float& lo, float& hi) {
    unsigned a, b;
    asm("mov.b64 {%0, %1}, %2;" : "=r"(a), "=r"(b) : "l"(p));
    lo = __uint_as_float(a);
    hi = __uint_as_float(b);
}
__device__ __forceinline__ void fma2(unsigned long long& acc, unsigned long long a,
                                     unsigned long long b) {
    asm volatile("fma.rn.f32x2 %0, %1, %2, %0;" : "+l"(acc) : "l"(a), "l"(b));
}
// 16-byte shared load as two packed f32x2 operands
__device__ __forceinline__ void lds_v2u64(unsigned addr, unsigned long long& w01,
                                          unsigned long long& w23) {
    asm volatile("ld.shared.v2.u64 {%0, %1}, [%2];" : "=l"(w01), "=l"(w23) : "r"(addr));
}
// vectorized no-return global reduction (sm_90+); explicit global-space address
__device__ __forceinline__ void red_add_v4(float* ptr, float4 v) {
    unsigned long long gaddr = __cvta_generic_to_global(ptr);
    asm volatile("red.global.add.v4.f32 [%0], {%1, %2, %3, %4};"
                 :: "l"(gaddr), "f"(v.x), "f"(v.y), "f"(v.z), "f"(v.w) : "memory");
}

// ---------- init: zero cnt, copy x into working buffer ----------
__global__ void __launch_bounds__(256) k_init(const float* __restrict__ x, int n) {
    int i = blockIdx.x * blockDim.x + threadIdx.x;
    if (i < n) {
        g_cnt[i] = 0.f;
        g_x[i * 3 + 0] = x[i * 3 + 0];
        g_x[i * 3 + 1] = x[i * 3 + 1];
        g_x[i * 3 + 2] = x[i * 3 + 2];
    }
}

// ---------- in-degree count ----------
__global__ void __launch_bounds__(256) k_cnt(const int* __restrict__ row, int E) {
    int e = blockIdx.x * blockDim.x + threadIdx.x;
    if (e < E) atomicAdd(&g_cnt[row[e]], 1.0f);
}

// ---------- embedding_in: g_h = h @ W[21,64] + b ----------
__global__ void __launch_bounds__(256) k_embed(const float* __restrict__ h,
                                               const float* __restrict__ W,
                                               const float* __restrict__ b, int n) {
    __shared__ float sW[21][64];
    __shared__ float sb[64];
    int tid = threadIdx.x;
    for (int idx = tid; idx < 21 * 64; idx += 256) sW[idx / 64][idx % 64] = W[idx];
    if (tid < 64) sb[tid] = b[tid];
    __syncthreads();
    int warp = tid >> 5, lane = tid & 31;
    int i = blockIdx.x * 8 + warp;
    if (i >= n) return;
    float hv = (lane < 21) ? h[i * 21 + lane] : 0.f;
    float a0 = sb[lane], a1 = sb[lane + 32];
#pragma unroll
    for (int k = 0; k < 21; k++) {
        float v = __shfl_sync(0xffffffffu, hv, k);
        a0 += v * sW[k][lane];
        a1 += v * sW[k][lane + 32];
    }
    g_h[i * 64 + lane] = a0;
    g_h[i * 64 + 32 + lane] = a1;
}

// ---------- standalone node precompute (layer 0): Pa/Pb from g_h; zero agg/trans ----------
__global__ void __launch_bounds__(256) k_node_pre(const float* __restrict__ W1,  // [129][64]
                                                  const float* __restrict__ b1, int n) {
    __shared__ float2 sWa[64][32];
    __shared__ float2 sWb[64][32];
    __shared__ float sb1[64];
    int tid = threadIdx.x;
    for (int idx = tid; idx < 64 * 32; idx += 256) {
        int k = idx >> 5, j = idx & 31;
        sWa[k][j] = make_float2(W1[k * 64 + j], W1[k * 64 + j + 32]);
        sWb[k][j] = make_float2(W1[(k + 64) * 64 + j], W1[(k + 64) * 64 + j + 32]);
    }
    if (tid < 64) sb1[tid] = b1[tid];
    __syncthreads();
    int warp = tid >> 5, lane = tid & 31;
    int i = blockIdx.x * 8 + warp;
    if (i >= n) return;
    float h0 = g_h[i * 64 + lane], h1 = g_h[i * 64 + 32 + lane];
    float a0 = sb1[lane], a1 = sb1[lane + 32];   // fold edge bias b1 into Pa
    float c0 = 0.f, c1 = 0.f;
#pragma unroll
    for (int k = 0; k < 64; k++) {
        float v = (k < 32) ? __shfl_sync(0xffffffffu, h0, k)
                           : __shfl_sync(0xffffffffu, h1, k - 32);
        float2 wa = sWa[k][lane];
        float2 wb = sWb[k][lane];
        a0 += v * wa.x; a1 += v * wa.y;
        c0 += v * wb.x; c1 += v * wb.y;
    }
    g_Pa[i * 64 + lane] = a0;
    g_Pa[i * 64 + 32 + lane] = a1;
    g_Pb[i * 64 + lane] = c0;
    g_Pb[i * 64 + 32 + lane] = c1;
    g_agg[i * 64 + lane] = 0.f;
    g_agg[i * 64 + 32 + lane] = 0.f;
    if (lane < 3) g_trans[i * 3 + lane] = 0.f;
}

// ---------- persistent edge kernel: m1 -> m -> s, plus reduction aggregation ----------
__global__ void __launch_bounds__(256) k_edge(
    const int* __restrict__ row, const int* __restrict__ col,
    const float* __restrict__ w1c,               // [64] radial row of edge_w1
    const float* __restrict__ W2, const float* __restrict__ b2,
    const float* __restrict__ Cw1, const float* __restrict__ cb1,
    const float* __restrict__ Cw2, int E, int nTiles) {
    __shared__ __align__(16) float sW2[64 * 64];
    __shared__ __align__(16) float sC1[64 * 64];
    __shared__ __align__(16) float sT[TE * 64];   // m1, then m (reused)
    __shared__ float svec[256];                   // [w1c | b2 | cb1 | Cw2]
    __shared__ float sdiff[TE][3];
    __shared__ int   srow[TE];
    __shared__ float sS[TE];

    int tid = threadIdx.x;
    // ---- one-time weight staging ----
    for (int idx = tid; idx < 1024; idx += 256) {
        ((float4*)sW2)[idx] = ((const float4*)W2)[idx];
        ((float4*)sC1)[idx] = ((const float4*)Cw1)[idx];
    }
    if (tid < 64)       svec[tid] = w1c[tid];
    else if (tid < 128) svec[tid] = b2[tid - 64];
    else if (tid < 192) svec[tid] = cb1[tid - 128];
    else                svec[tid] = Cw2[tid - 192];

    int tx = tid & 15, ty = tid >> 4;  // j = tx*4+jj ; edges e = ty*2+i
    int e0 = ty * 2, e1 = ty * 2 + 1;
    int jb = tx * 4;
    unsigned sW2a = (unsigned)__cvta_generic_to_shared(sW2) + jb * 4;
    unsigned sC1a = (unsigned)__cvta_generic_to_shared(sC1) + jb * 4;
    const float4* sT0v = (const float4*)(sT + e0 * 64);
    const float4* sT1v = (const float4*)(sT + e1 * 64);

    // ---- index prefetch for the first tile (r = -1 marks invalid edge) ----
    int pr[2] = {-1, -1}, pc[2] = {0, 0};
    {
        int t0i = blockIdx.x;
        if (t0i < nTiles) {
            int eb = t0i * TE;
            int nE = min(TE, E - eb);
#pragma unroll
            for (int i = 0; i < 2; i++) {
                int e = ty * 2 + i;
                if (e < nE) { pr[i] = row[eb + e]; pc[i] = col[eb + e]; }
            }
        }
    }

    for (int tile = blockIdx.x; tile < nTiles; tile += gridDim.x) {
        int eb = tile * TE;
        int nE = min(TE, E - eb);
        int cr[2] = {pr[0], pr[1]}, cc[2] = {pc[0], pc[1]};
        __syncthreads();  // previous tile fully consumed (covers sT/sS/srow/sdiff reuse
                          // and, on the first iteration, the weight staging above)

        // ---- stage 1 (fused setup): use prefetched indices, gather Pa/Pb now ----
#pragma unroll
        for (int i = 0; i < 2; i++) {
            int e = ty * 2 + i;
            int r = cr[i], c = cc[i];
            float4 res;
            if (r >= 0) {
                float4 pa = *(const float4*)(g_Pa + r * 64 + jb);   // issue gathers early
                float4 pb = *(const float4*)(g_Pb + c * 64 + jb);
                float dx = g_x[r * 3 + 0] - g_x[c * 3 + 0];
                float dy = g_x[r * 3 + 1] - g_x[c * 3 + 1];
                float dz = g_x[r * 3 + 2] - g_x[c * 3 + 2];
                float rad = dx * dx + dy * dy + dz * dz;
                if (tx == 0) {                 // one writer per edge for stage-5 data
                    srow[e] = r;
                    sdiff[e][0] = dx; sdiff[e][1] = dy; sdiff[e][2] = dz;
                }
                res.x = silu_f(pa.x + pb.x + rad * svec[jb + 0]);
                res.y = silu_f(pa.y + pb.y + rad * svec[jb + 1]);
                res.z = silu_f(pa.z + pb.z + rad * svec[jb + 2]);
                res.w = silu_f(pa.w + pb.w + rad * svec[jb + 3]);
            } else {
                if (tx == 0) {
                    srow[e] = 0;
                    sdiff[e][0] = sdiff[e][1] = sdiff[e][2] = 0.f;
                }
                res = make_float4(0.f, 0.f, 0.f, 0.f);
            }
            ((float4*)(sT + e * 64))[tx] = res;
        }

        // ---- prefetch next tile's indices (latency hidden behind stages 2-5) ----
        pr[0] = pr[1] = -1;
        {
            int tn = tile + gridDim.x;
            if (tn < nTiles) {
                int ebn = tn * TE;
                int nEn = min(TE, E - ebn);
#pragma unroll
                for (int i = 0; i < 2; i++) {
                    int e = ty * 2 + i;
                    if (e < nEn) { pr[i] = row[ebn + e]; pc[i] = col[ebn + e]; }
                }
            }
        }
        __syncthreads();  // sT = m1 ready; srow/sdiff ready

        // ---- stage 2: m = silu(m1 @ W2 + b2), acc in regs (packed f32x2) ----
        unsigned long long acc00, acc01, acc10, acc11;
        {
            unsigned long long bias01 = pack2(svec[64 + jb], svec[64 + jb + 1]);
            unsigned long long bias23 = pack2(svec[64 + jb + 2], svec[64 + jb + 3]);
            acc00 = bias01; acc01 = bias23; acc10 = bias01; acc11 = bias23;
#pragma unroll 4
            for (int kb = 0; kb < 16; kb++) {
                float4 av0 = sT0v[kb];    // activations for 4 k-steps, edge e0
                float4 av1 = sT1v[kb];    // activations for 4 k-steps, edge e1
                const float* a0p = (const float*)&av0;
                const float* a1p = (const float*)&av1;
#pragma unroll
                for (int kk = 0; kk < 4; kk++) {
                    unsigned long long w01, w23;
                    lds_v2u64(sW2a + (unsigned)((kb * 4 + kk) * 256), w01, w23);
                    unsigned long long a0 = bcast2(a0p[kk]);
                    unsigned long long a1 = bcast2(a1p[kk]);
                    fma2(acc00, a0, w01); fma2(acc01, a0, w23);
                    fma2(acc10, a1, w01); fma2(acc11, a1, w23);
                }
            }
        }
        __syncthreads();  // all reads of m1 done -> sT reusable
        {
            float v0, v1, v2, v3;
            unpack2(acc00, v0, v1); unpack2(acc01, v2, v3);
            ((float4*)(sT + e0 * 64))[tx] =
                make_float4(silu_f(v0), silu_f(v1), silu_f(v2), silu_f(v3));
            unpack2(acc10, v0, v1); unpack2(acc11, v2, v3);
            ((float4*)(sT + e1 * 64))[tx] =
                make_float4(silu_f(v0), silu_f(v1), silu_f(v2), silu_f(v3));
        }
        __syncthreads();  // sT = m ready

        // ---- stage 3+4: cmid = silu(m @ Cw1 + cb1); s = cmid . Cw2 (regs + shfl) ----
        {
            unsigned long long bias01 = pack2(svec[128 + jb], svec[128 + jb + 1]);
            unsigned long long bias23 = pack2(svec[128 + jb + 2], svec[128 + jb + 3]);
            acc00 = bias01; acc01 = bias23; acc10 = bias01; acc11 = bias23;
#pragma unroll 4
            for (int kb = 0; kb < 16; kb++) {
                float4 av0 = sT0v[kb];
                float4 av1 = sT1v[kb];
                const float* a0p = (const float*)&av0;
                const float* a1p = (const float*)&av1;
#pragma unroll
                for (int kk = 0; kk < 4; kk++) {
                    unsigned long long w01, w23;
                    lds_v2u64(sC1a + (unsigned)((kb * 4 + kk) * 256), w01, w23);
                    unsigned long long a0 = bcast2(a0p[kk]);
                    unsigned long long a1 = bcast2(a1p[kk]);
                    fma2(acc00, a0, w01); fma2(acc01, a0, w23);
                    fma2(acc10, a1, w01); fma2(acc11, a1, w23);
                }
            }
            float c0, c1, c2, c3;
            float cw0 = svec[192 + jb], cw1v = svec[192 + jb + 1];
            float cw2v = svec[192 + jb + 2], cw3 = svec[192 + jb + 3];
            unpack2(acc00, c0, c1); unpack2(acc01, c2, c3);
            float p0 = silu_f(c0) * cw0 + silu_f(c1) * cw1v +
                       silu_f(c2) * cw2v + silu_f(c3) * cw3;
            unpack2(acc10, c0, c1); unpack2(acc11, c2, c3);
            float p1 = silu_f(c0) * cw0 + silu_f(c1) * cw1v +
                       silu_f(c2) * cw2v + silu_f(c3) * cw3;
#pragma unroll
            for (int o = 1; o < 16; o <<= 1) {
                p0 += __shfl_xor_sync(0xffffffffu, p0, o);
                p1 += __shfl_xor_sync(0xffffffffu, p1, o);
            }
            if (tx == 0) { sS[e0] = p0; sS[e1] = p1; }
        }
        __syncthreads();  // sS ready; sT(m) still valid

        // ---- stage 5: vectorized reduction aggregation (red.global.add.v4) ----
        for (int idx = tid; idx < TE * 16; idx += 256) {
            int e = idx >> 4, jg = (idx & 15) * 4;
            if (e < nE) {
                float4 v = *(const float4*)(sT + e * 64 + jg);
                red_add_v4(g_agg + srow[e] * 64 + jg, v);
            }
        }
        if (tid < TE * 3) {
            int e = tid / 3, d = tid - e * 3;
            if (e < nE) atomicAdd(&g_trans[srow[e] * 3 + d], sdiff[e][d] * sS[e]);
        }
    }
}

// ---------- fused node update + next-layer precompute (layers 0..2) ----------
// Phase A: x += trans/cnt ; h += node_mlp([h, agg])        (W1 32KB + W2 16KB shared)
// Phase B: Pa/Pb = h @ next edge_w1 halves (+ b1 fold); zero agg/trans
//          (reloads the SAME 48KB shared buffer with Wa/Wb after a barrier).
// No early returns: all threads reach both barriers; i-ops are predicated.
__global__ void __launch_bounds__(256) k_node_fused(
    const float* __restrict__ W1, const float* __restrict__ b1,     // node mlp
    const float* __restrict__ W2, const float* __restrict__ b2,
    const float* __restrict__ eW1, const float* __restrict__ eb1,   // next layer edge [129][64]
    int n) {
    __shared__ __align__(16) char smem[49152];
    float2 (*sW1)[32] = (float2(*)[32])smem;             // [128][32] = 32KB
    float2 (*sW2)[32] = (float2(*)[32])(smem + 32768);   // [64][32]  = 16KB
    int tid = threadIdx.x;
    for (int idx = tid; idx < 128 * 32; idx += 256) {
        int k = idx >> 5, j = idx & 31;
        sW1[k][j] = make_float2(W1[k * 64 + j], W1[k * 64 + j + 32]);
    }
    for (int idx = tid; idx < 64 * 32; idx += 256) {
        int k = idx >> 5, j = idx & 31;
        sW2[k][j] = make_float2(W2[k * 64 + j], W2[k * 64 + j + 32]);
    }
    __syncthreads();
    int warp = tid >> 5, lane = tid & 31;
    int i = blockIdx.x * 8 + warp;
    bool act = (i < n);

    float h0 = 0.f, h1 = 0.f;
    if (act) {
        if (lane < 3) {
            float cnt = fmaxf(g_cnt[i], 1.0f);
            g_x[i * 3 + lane] += g_trans[i * 3 + lane] / cnt;
        }
        h0 = g_h[i * 64 + lane];
        h1 = g_h[i * 64 + 32 + lane];
        float a0 = g_agg[i * 64 + lane], a1 = g_agg[i * 64 + 32 + lane];
        float t0 = __ldg(b1 + lane), t1 = __ldg(b1 + lane + 32);
#pragma unroll
        for (int k = 0; k < 128; k++) {
            float v;
            if (k < 32)       v = __shfl_sync(0xffffffffu, h0, k);
            else if (k < 64)  v = __shfl_sync(0xffffffffu, h1, k - 32);
            else if (k < 96)  v = __shfl_sync(0xffffffffu, a0, k - 64);
            else              v = __shfl_sync(0xffffffffu, a1, k - 96);
            float2 w = sW1[k][lane];
            t0 += v * w.x;
            t1 += v * w.y;
        }
        t0 = silu_f(t0);
        t1 = silu_f(t1);
        float o0 = __ldg(b2 + lane), o1 = __ldg(b2 + lane + 32);
#pragma unroll
        for (int k = 0; k < 64; k++) {
            float v = (k < 32) ? __shfl_sync(0xffffffffu, t0, k)
                               : __shfl_sync(0xffffffffu, t1, k - 32);
            float2 w = sW2[k][lane];
            o0 += v * w.x;
            o1 += v * w.y;
        }
        h0 += o0;
        h1 += o1;
        g_h[i * 64 + lane] = h0;
        g_h[i * 64 + 32 + lane] = h1;
    }
    __syncthreads();  // phase A shared reads complete -> overlay

    // ---- phase B: reload shared with next layer's edge W1 halves ----
    float2 (*sWa)[32] = (float2(*)[32])smem;             // [64][32] = 16KB
    float2 (*sWb)[32] = (float2(*)[32])(smem + 16384);   // [64][32] = 16KB
    for (int idx = tid; idx < 64 * 32; idx += 256) {
        int k = idx >> 5, j = idx & 31;
        sWa[k][j] = make_float2(eW1[k * 64 + j], eW1[k * 64 + j + 32]);
        sWb[k][j] = make_float2(eW1[(k + 64) * 64 + j], eW1[(k + 64) * 64 + j + 32]);
    }
    __syncthreads();

    if (act) {
        float a0 = __ldg(eb1 + lane), a1 = __ldg(eb1 + lane + 32);  // fold edge b1 into Pa
        float c0 = 0.f, c1 = 0.f;
#pragma unroll
        for (int k = 0; k < 64; k++) {
            float v = (k < 32) ? __shfl_sync(0xffffffffu, h0, k)
                               : __shfl_sync(0xffffffffu, h1, k - 32);
            float2 wa = sWa[k][lane];
            float2 wb = sWb[k][lane];
            a0 += v * wa.x; a1 += v * wa.y;
            c0 += v * wb.x; c1 += v * wb.y;
        }
        g_Pa[i * 64 + lane] = a0;
        g_Pa[i * 64 + 32 + lane] = a1;
        g_Pb[i * 64 + lane] = c0;
        g_Pb[i * 64 + 32 + lane] = c1;
        g_agg[i * 64 + lane] = 0.f;
        g_agg[i * 64 + 32 + lane] = 0.f;
        if (lane < 3) g_trans[i * 3 + lane] = 0.f;
    }
}

// ---------- fused LAST node update + embedding_out + head (layer 3) ----------
// Phase A: x += trans/cnt ; h += node_mlp([h, agg])  (h kept in registers)
// Phase B: out = relu((h@We+be)@Hw1+hb1)@Hw2+hb2, written straight to d_out.
__global__ void __launch_bounds__(256) k_node_last(
    const float* __restrict__ W1, const float* __restrict__ b1,     // node mlp
    const float* __restrict__ W2, const float* __restrict__ b2,
    const float* __restrict__ We, const float* __restrict__ be,     // emb_out
    const float* __restrict__ Hw1, const float* __restrict__ hb1,   // head
    const float* __restrict__ Hw2, const float* __restrict__ hb2,
    float* __restrict__ out, int n) {
    __shared__ __align__(16) char smem[49152];
    int tid = threadIdx.x;
    int warp = tid >> 5, lane = tid & 31;
    int i = blockIdx.x * 8 + warp;
    bool act = (i < n);

    // ---- phase A layout: node W1 [128][32] (32KB) + node W2 [64][32] (16KB) ----
    {
        float2 (*sW1)[32] = (float2(*)[32])smem;
        float2 (*sW2)[32] = (float2(*)[32])(smem + 32768);
        for (int idx = tid; idx < 128 * 32; idx += 256) {
            int k = idx >> 5, j = idx & 31;
            sW1[k][j] = make_float2(W1[k * 64 + j], W1[k * 64 + j + 32]);
        }
        for (int idx = tid; idx < 64 * 32; idx += 256) {
            int k = idx >> 5, j = idx & 31;
            sW2[k][j] = make_float2(W2[k * 64 + j], W2[k * 64 + j + 32]);
        }
        __syncthreads();

        float h0 = 0.f, h1 = 0.f;
        if (act) {
            if (lane < 3) {
                float cnt = fmaxf(g_cnt[i], 1.0f);
                g_x[i * 3 + lane] += g_trans[i * 3 + lane] / cnt;
            }
            h0 = g_h[i * 64 + lane];
            h1 = g_h[i * 64 + 32 + lane];
            float a0 = g_agg[i * 64 + lane], a1 = g_agg[i * 64 + 32 + lane];
            float t0 = __ldg(b1 + lane), t1 = __ldg(b1 + lane + 32);
#pragma unroll
            for (int k = 0; k < 128; k++) {
                float v;
                if (k < 32)       v = __shfl_sync(0xffffffffu, h0, k);
                else if (k < 64)  v = __shfl_sync(0xffffffffu, h1, k - 32);
                else if (k < 96)  v = __shfl_sync(0xffffffffu, a0, k - 64);
                else              v = __shfl_sync(0xffffffffu, a1, k - 96);
                float2 w = sW1[k][lane];
                t0 += v * w.x;
                t1 += v * w.y;
            }
            t0 = silu_f(t0);
            t1 = silu_f(t1);
            float o0 = __ldg(b2 + lane), o1 = __ldg(b2 + lane + 32);
#pragma unroll
            for (int k = 0; k < 64; k++) {
                float v = (k < 32) ? __shfl_sync(0xffffffffu, t0, k)
                                   : __shfl_sync(0xffffffffu, t1, k - 32);
                float2 w = sW2[k][lane];
                o0 += v * w.x;
                o1 += v * w.y;
            }
            h0 += o0;
            h1 += o1;
        }
        __syncthreads();  // phase A shared reads complete -> overlay

        // ---- phase B layout: We [64][32] f2 (16KB) + Hw1 [64][32] f2 (16KB)
        //      + Hw2 [64][20] f (5120B) + biases (be, hb1: 256B each; hb2: 80B) ----
        float2 (*sWe)[32] = (float2(*)[32])smem;
        float2 (*sH1)[32] = (float2(*)[32])(smem + 16384);
        float  (*sH2)[20] = (float(*)[20])(smem + 32768);
        float* sbe  = (float*)(smem + 32768 + 5120);
        float* shb1 = sbe + 64;
        float* shb2 = shb1 + 64;
        for (int idx = tid; idx < 64 * 32; idx += 256) {
            int k = idx >> 5, j = idx & 31;
            sWe[k][j] = make_float2(We[k * 64 + j], We[k * 64 + j + 32]);
            sH1[k][j] = make_float2(Hw1[k * 64 + j], Hw1[k * 64 + j + 32]);
        }
        for (int idx = tid; idx < 64 * 20; idx += 256) sH2[idx / 20][idx % 20] = Hw2[idx];
        if (tid < 64) { sbe[tid] = be[tid]; shb1[tid] = hb1[tid]; }
        if (tid >= 64 && tid < 84) shb2[tid - 64] = hb2[tid - 64];
        __syncthreads();

        if (act) {
            // embedding_out
            float e0 = sbe[lane], e1 = sbe[lane + 32];
#pragma unroll
            for (int k = 0; k < 64; k++) {
                float v = (k < 32) ? __shfl_sync(0xffffffffu, h0, k)
                                   : __shfl_sync(0xffffffffu, h1, k - 32);
                float2 w = sWe[k][lane];
                e0 += v * w.x;
                e1 += v * w.y;
            }
            // head layer 1 + relu
            float t0 = shb1[lane], t1 = shb1[lane + 32];
#pragma unroll
            for (int k = 0; k < 64; k++) {
                float v = (k < 32) ? __shfl_sync(0xffffffffu, e0, k)
                                   : __shfl_sync(0xffffffffu, e1, k - 32);
                float2 w = sH1[k][lane];
                t0 += v * w.x;
                t1 += v * w.y;
            }
            t0 = fmaxf(t0, 0.f);
            t1 = fmaxf(t1, 0.f);
            // head layer 2 (20 outputs)
            int jo = (lane < 20) ? lane : 0;
            float o = (lane < 20) ? shb2[lane] : 0.f;
#pragma unroll
            for (int k = 0; k < 64; k++) {
                float v = (k < 32) ? __shfl_sync(0xffffffffu, t0, k)
                                   : __shfl_sync(0xffffffffu, t1, k - 32);
                o += v * sH2[k][jo];
            }
            if (lane < 20) out[i * 20 + lane] = o;
        }
    }
}

extern "C" void kernel_launch(void* const* d_in, const int* in_sizes, int n_in,
                              void* d_out, int out_size) {
    const float* h         = (const float*)d_in[0];
    const float* x         = (const float*)d_in[1];
    const int*   edges     = (const int*)d_in[2];
    const float* emb_in_w  = (const float*)d_in[3];
    const float* emb_in_b  = (const float*)d_in[4];
    const float* emb_out_w = (const float*)d_in[5];
    const float* emb_out_b = (const float*)d_in[6];
    const float* edge_w1   = (const float*)d_in[7];
    const float* edge_b1   = (const float*)d_in[8];
    const float* edge_w2   = (const float*)d_in[9];
    const float* edge_b2   = (const float*)d_in[10];
    const float* node_w1   = (const float*)d_in[11];
    const float* node_b1   = (const float*)d_in[12];
    const float* node_w2   = (const float*)d_in[13];
    const float* node_b2   = (const float*)d_in[14];
    const float* coord_w1  = (const float*)d_in[15];
    const float* coord_b1  = (const float*)d_in[16];
    const float* coord_w2  = (const float*)d_in[17];
    const float* head_w1   = (const float*)d_in[18];
    const float* head_b1   = (const float*)d_in[19];
    const float* head_w2   = (const float*)d_in[20];
    const float* head_b2   = (const float*)d_in[21];
    float* out = (float*)d_out;

    int n = in_sizes[0] / 21;
    int E = in_sizes[2] / 2;
    const int* row = edges;
    const int* col = edges + E;

    int nb  = (n + 255) / 256;
    int nwb = (n + 7) / 8;          // warp-per-node blocks (8 warps/block)
    int nTiles = (E + TE - 1) / TE;
    int egrid = 740;                 // 148 SMs * 5 CTAs (~42 KB smem each)
    if (egrid > nTiles) egrid = nTiles;

    k_init<<<nb, 256>>>(x, n);
    k_cnt<<<(E + 255) / 256, 256>>>(row, E);
    k_embed<<<nwb, 256>>>(h, emb_in_w, emb_in_b, n);
    k_node_pre<<<nwb, 256>>>(edge_w1, edge_b1, n);   // layer 0 Pa/Pb

    for (int l = 0; l < 4; l++) {
        k_edge<<<egrid, 256>>>(row, col,
                               edge_w1 + l * 129 * 64 + 128 * 64,
                               edge_w2 + l * 4096, edge_b2 + l * 64,
                               coord_w1 + l * 4096, coord_b1 + l * 64,
                               coord_w2 + l * 64, E, nTiles);
        if (l < 3) {
            k_node_fused<<<nwb, 256>>>(node_w1 + l * 128 * 64, node_b1 + l * 64,
                                       node_w2 + l * 4096, node_b2 + l * 64,
                                       edge_w1 + (l + 1) * 129 * 64,
                                       edge_b1 + (l + 1) * 64, n);
        } else {
            k_node_last<<<nwb, 256>>>(node_w1 + l * 128 * 64, node_b1 + l * 64,
                                      node_w2 + l * 4096, node_b2 + l * 64,
                                      emb_out_w, emb_out_b,
                                      head_w1, head_b1, head_w2, head_b2,
                                      out, n);
        }
    }
}

// round 13
// speedup vs baseline: 1.1747x; 1.1747x over previous
#include <cuda_runtime.h>

#define NMAX 50000
#define EMAX 800000
#define HID 64
#define EW 6   // edges per warp-chunk in edge kernel

// ---------- scratch (device globals; no allocation allowed) ----------
__device__ float g_h[NMAX * HID];
__device__ float g_x[NMAX * 3];
__device__ float g_Pa[NMAX * HID];   // h @ W1a + b1  (gathered at row)
__device__ float g_Pb[NMAX * HID];   // h @ W1b       (gathered at col)
__device__ float g_agg[NMAX * HID];  // segment_sum of m
__device__ float g_trans[NMAX * 3];  // segment_sum of diff * s
__device__ float g_cnt[NMAX];

__device__ __forceinline__ float silu_f(float v) {
    return v * (1.0f / (1.0f + __expf(-v)));
}

__device__ __forceinline__ unsigned long long pack2(float lo, float hi) {
    unsigned long long r;
    asm("mov.b64 %0, {%1, %2};" : "=l"(r) : "r"(__float_as_uint(lo)), "r"(__float_as_uint(hi)));
    return r;
}
__device__ __forceinline__ unsigned long long bcast2(float v) {
    unsigned long long r;
    unsigned u = __float_as_uint(v);
    asm("mov.b64 %0, {%1, %1};" : "=l"(r) : "r"(u));
    return r;
}
__device__ __forceinline__ void unpack2(unsigned long long p, float& lo, float& hi) {
    unsigned a, b;
    asm("mov.b64 {%0, %1}, %2;" : "=r"(a), "=r"(b) : "l"(p));
    lo = __uint_as_float(a);
    hi = __uint_as_float(b);
}
__device__ __forceinline__ void fma2(unsigned long long& acc, unsigned long long a,
                                     unsigned long long b) {
    asm volatile("fma.rn.f32x2 %0, %1, %2, %0;" : "+l"(acc) : "l"(a), "l"(b));
}
// 16-byte shared load as two packed f32x2 operands
__device__ __forceinline__ void lds_v2u64(unsigned addr, unsigned long long& w01,
                                          unsigned long long& w23) {
    asm volatile("ld.shared.v2.u64 {%0, %1}, [%2];" : "=l"(w01), "=l"(w23) : "r"(addr));
}
// vectorized no-return global reduction (sm_90+); explicit global-space address
__device__ __forceinline__ void red_add_v4(float* ptr, float4 v) {
    unsigned long long gaddr = __cvta_generic_to_global(ptr);
    asm volatile("red.global.add.v4.f32 [%0], {%1, %2, %3, %4};"
                 :: "l"(gaddr), "f"(v.x), "f"(v.y), "f"(v.z), "f"(v.w) : "memory");
}

// ---------- init: zero cnt, copy x into working buffer ----------
__global__ void __launch_bounds__(256) k_init(const float* __restrict__ x, int n) {
    int i = blockIdx.x * blockDim.x + threadIdx.x;
    if (i < n) {
        g_cnt[i] = 0.f;
        g_x[i * 3 + 0] = x[i * 3 + 0];
        g_x[i * 3 + 1] = x[i * 3 + 1];
        g_x[i * 3 + 2] = x[i * 3 + 2];
    }
}

// ---------- in-degree count ----------
__global__ void __launch_bounds__(256) k_cnt(const int* __restrict__ row, int E) {
    int e = blockIdx.x * blockDim.x + threadIdx.x;
    if (e < E) atomicAdd(&g_cnt[row[e]], 1.0f);
}

// ---------- embedding_in: g_h = h @ W[21,64] + b ----------
__global__ void __launch_bounds__(256) k_embed(const float* __restrict__ h,
                                               const float* __restrict__ W,
                                               const float* __restrict__ b, int n) {
    __shared__ float sW[21][64];
    __shared__ float sb[64];
    int tid = threadIdx.x;
    for (int idx = tid; idx < 21 * 64; idx += 256) sW[idx / 64][idx % 64] = W[idx];
    if (tid < 64) sb[tid] = b[tid];
    __syncthreads();
    int warp = tid >> 5, lane = tid & 31;
    int i = blockIdx.x * 8 + warp;
    if (i >= n) return;
    float hv = (lane < 21) ? h[i * 21 + lane] : 0.f;
    float a0 = sb[lane], a1 = sb[lane + 32];
#pragma unroll
    for (int k = 0; k < 21; k++) {
        float v = __shfl_sync(0xffffffffu, hv, k);
        a0 += v * sW[k][lane];
        a1 += v * sW[k][lane + 32];
    }
    g_h[i * 64 + lane] = a0;
    g_h[i * 64 + 32 + lane] = a1;
}

// ---------- standalone node precompute (layer 0): Pa/Pb from g_h; zero agg/trans ----------
__global__ void __launch_bounds__(256) k_node_pre(const float* __restrict__ W1,  // [129][64]
                                                  const float* __restrict__ b1, int n) {
    __shared__ float2 sWa[64][32];
    __shared__ float2 sWb[64][32];
    __shared__ float sb1[64];
    int tid = threadIdx.x;
    for (int idx = tid; idx < 64 * 32; idx += 256) {
        int k = idx >> 5, j = idx & 31;
        sWa[k][j] = make_float2(W1[k * 64 + j], W1[k * 64 + j + 32]);
        sWb[k][j] = make_float2(W1[(k + 64) * 64 + j], W1[(k + 64) * 64 + j + 32]);
    }
    if (tid < 64) sb1[tid] = b1[tid];
    __syncthreads();
    int warp = tid >> 5, lane = tid & 31;
    int i = blockIdx.x * 8 + warp;
    if (i >= n) return;
    float h0 = g_h[i * 64 + lane], h1 = g_h[i * 64 + 32 + lane];
    float a0 = sb1[lane], a1 = sb1[lane + 32];   // fold edge bias b1 into Pa
    float c0 = 0.f, c1 = 0.f;
#pragma unroll
    for (int k = 0; k < 64; k++) {
        float v = (k < 32) ? __shfl_sync(0xffffffffu, h0, k)
                           : __shfl_sync(0xffffffffu, h1, k - 32);
        float2 wa = sWa[k][lane];
        float2 wb = sWb[k][lane];
        a0 += v * wa.x; a1 += v * wa.y;
        c0 += v * wb.x; c1 += v * wb.y;
    }
    g_Pa[i * 64 + lane] = a0;
    g_Pa[i * 64 + 32 + lane] = a1;
    g_Pb[i * 64 + lane] = c0;
    g_Pb[i * 64 + 32 + lane] = c1;
    g_agg[i * 64 + lane] = 0.f;
    g_agg[i * 64 + 32 + lane] = 0.f;
    if (lane < 3) g_trans[i * 3 + lane] = 0.f;
}

// ---------- warp-autonomous edge kernel: each warp owns EW edges end-to-end ----------
// No CTA barriers in the main loop; per-warp activation buffer + __syncwarp only.
__global__ void __launch_bounds__(256) k_edge(
    const int* __restrict__ row, const int* __restrict__ col,
    const float* __restrict__ w1c,               // [64] radial row of edge_w1
    const float* __restrict__ W2, const float* __restrict__ b2,
    const float* __restrict__ Cw1, const float* __restrict__ cb1,
    const float* __restrict__ Cw2, int E, int nChunks) {
    __shared__ __align__(16) float sW2[64 * 64];      // 16KB
    __shared__ __align__(16) float sC1[64 * 64];      // 16KB
    __shared__ __align__(16) float sAct[8][EW * 64];  // 12KB (per-warp)
    __shared__ int   sRow[8][EW];
    __shared__ float sDiff[8][EW][3];
    __shared__ float sSv[8][EW];
    __shared__ float svec[256];                       // [w1c | b2 | cb1 | Cw2]

    int tid = threadIdx.x, wid = tid >> 5, lane = tid & 31;
    // ---- one-time weight staging (only CTA barrier in the kernel) ----
    for (int idx = tid; idx < 1024; idx += 256) {
        ((float4*)sW2)[idx] = ((const float4*)W2)[idx];
        ((float4*)sC1)[idx] = ((const float4*)Cw1)[idx];
    }
    if (tid < 64)       svec[tid] = w1c[tid];
    else if (tid < 128) svec[tid] = b2[tid - 64];
    else if (tid < 192) svec[tid] = cb1[tid - 128];
    else                svec[tid] = Cw2[tid - 192];
    __syncthreads();

    int tx = lane & 15, th = lane >> 4;   // 16 col-lanes x 2 half-warps
    int jb = tx * 4;
    float* actw = sAct[wid];
    unsigned sW2a = (unsigned)__cvta_generic_to_shared(sW2) + jb * 4;
    unsigned sC1a = (unsigned)__cvta_generic_to_shared(sC1) + jb * 4;

    int gw = blockIdx.x * 8 + wid;       // global warp id
    int wstride = gridDim.x * 8;

    // ---- index prefetch for the first chunk (r = -1 marks invalid edge) ----
    int pr[3], pc[3];
#pragma unroll
    for (int i = 0; i < 3; i++) { pr[i] = -1; pc[i] = 0; }
    if (gw < nChunks) {
#pragma unroll
        for (int i = 0; i < 3; i++) {
            int ge = gw * EW + th * 3 + i;
            if (ge < E) { pr[i] = row[ge]; pc[i] = col[ge]; }
        }
    }

    for (int ch = gw; ch < nChunks; ch += wstride) {
        int base = ch * EW;
        int cr[3] = {pr[0], pr[1], pr[2]}, cc[3] = {pc[0], pc[1], pc[2]};

        // ---- stage 1: m1 = silu(Pa[r] + Pb[c] + radial * w1c) -> actw ----
#pragma unroll
        for (int i = 0; i < 3; i++) {
            int el = th * 3 + i;
            int r = cr[i], c = cc[i];
            float4 res;
            if (r >= 0) {
                float4 pa = *(const float4*)(g_Pa + r * 64 + jb);
                float4 pb = *(const float4*)(g_Pb + c * 64 + jb);
                float dx = g_x[r * 3 + 0] - g_x[c * 3 + 0];
                float dy = g_x[r * 3 + 1] - g_x[c * 3 + 1];
                float dz = g_x[r * 3 + 2] - g_x[c * 3 + 2];
                float rad = dx * dx + dy * dy + dz * dz;
                if (tx == 0) {
                    sRow[wid][el] = r;
                    sDiff[wid][el][0] = dx; sDiff[wid][el][1] = dy; sDiff[wid][el][2] = dz;
                }
                res.x = silu_f(pa.x + pb.x + rad * svec[jb + 0]);
                res.y = silu_f(pa.y + pb.y + rad * svec[jb + 1]);
                res.z = silu_f(pa.z + pb.z + rad * svec[jb + 2]);
                res.w = silu_f(pa.w + pb.w + rad * svec[jb + 3]);
            } else {
                if (tx == 0) {
                    sRow[wid][el] = 0;
                    sDiff[wid][el][0] = sDiff[wid][el][1] = sDiff[wid][el][2] = 0.f;
                }
                res = make_float4(0.f, 0.f, 0.f, 0.f);
            }
            ((float4*)(actw + el * 64))[tx] = res;
        }
        // prefetch next chunk's indices (latency hidden behind stages 2-5)
        pr[0] = pr[1] = pr[2] = -1;
        {
            int cn = ch + wstride;
            if (cn < nChunks) {
#pragma unroll
                for (int i = 0; i < 3; i++) {
                    int ge = cn * EW + th * 3 + i;
                    if (ge < E) { pr[i] = row[ge]; pc[i] = col[ge]; }
                }
            }
        }
        __syncwarp();   // actw = m1 ready; meta ready

        // ---- stage 2: m = silu(m1 @ W2 + b2), acc in regs (packed f32x2) ----
        unsigned long long acc[3][2];
        {
            unsigned long long bias01 = pack2(svec[64 + jb], svec[64 + jb + 1]);
            unsigned long long bias23 = pack2(svec[64 + jb + 2], svec[64 + jb + 3]);
#pragma unroll
            for (int i = 0; i < 3; i++) { acc[i][0] = bias01; acc[i][1] = bias23; }
            const float4* av0 = (const float4*)(actw + (th * 3 + 0) * 64);
            const float4* av1 = (const float4*)(actw + (th * 3 + 1) * 64);
            const float4* av2 = (const float4*)(actw + (th * 3 + 2) * 64);
#pragma unroll 4
            for (int kb = 0; kb < 16; kb++) {
                float4 a0 = av0[kb], a1 = av1[kb], a2 = av2[kb];
                const float* p0 = (const float*)&a0;
                const float* p1 = (const float*)&a1;
                const float* p2 = (const float*)&a2;
#pragma unroll
                for (int kk = 0; kk < 4; kk++) {
                    unsigned long long w01, w23;
                    lds_v2u64(sW2a + (unsigned)((kb * 4 + kk) * 256), w01, w23);
                    unsigned long long b0 = bcast2(p0[kk]);
                    unsigned long long b1 = bcast2(p1[kk]);
                    unsigned long long b2v = bcast2(p2[kk]);
                    fma2(acc[0][0], b0, w01); fma2(acc[0][1], b0, w23);
                    fma2(acc[1][0], b1, w01); fma2(acc[1][1], b1, w23);
                    fma2(acc[2][0], b2v, w01); fma2(acc[2][1], b2v, w23);
                }
            }
        }
        __syncwarp();   // all reads of m1 done -> actw reusable
#pragma unroll
        for (int i = 0; i < 3; i++) {
            float v0, v1, v2, v3;
            unpack2(acc[i][0], v0, v1); unpack2(acc[i][1], v2, v3);
            ((float4*)(actw + (th * 3 + i) * 64))[tx] =
                make_float4(silu_f(v0), silu_f(v1), silu_f(v2), silu_f(v3));
        }
        __syncwarp();   // actw = m ready

        // ---- stage 3+4: cmid = silu(m @ Cw1 + cb1); s = cmid . Cw2 ----
        {
            unsigned long long bias01 = pack2(svec[128 + jb], svec[128 + jb + 1]);
            unsigned long long bias23 = pack2(svec[128 + jb + 2], svec[128 + jb + 3]);
#pragma unroll
            for (int i = 0; i < 3; i++) { acc[i][0] = bias01; acc[i][1] = bias23; }
            const float4* av0 = (const float4*)(actw + (th * 3 + 0) * 64);
            const float4* av1 = (const float4*)(actw + (th * 3 + 1) * 64);
            const float4* av2 = (const float4*)(actw + (th * 3 + 2) * 64);
#pragma unroll 4
            for (int kb = 0; kb < 16; kb++) {
                float4 a0 = av0[kb], a1 = av1[kb], a2 = av2[kb];
                const float* p0 = (const float*)&a0;
                const float* p1 = (const float*)&a1;
                const float* p2 = (const float*)&a2;
#pragma unroll
                for (int kk = 0; kk < 4; kk++) {
                    unsigned long long w01, w23;
                    lds_v2u64(sC1a + (unsigned)((kb * 4 + kk) * 256), w01, w23);
                    unsigned long long b0 = bcast2(p0[kk]);
                    unsigned long long b1 = bcast2(p1[kk]);
                    unsigned long long b2v = bcast2(p2[kk]);
                    fma2(acc[0][0], b0, w01); fma2(acc[0][1], b0, w23);
                    fma2(acc[1][0], b1, w01); fma2(acc[1][1], b1, w23);
                    fma2(acc[2][0], b2v, w01); fma2(acc[2][1], b2v, w23);
                }
            }
            float cw0 = svec[192 + jb], cw1v = svec[192 + jb + 1];
            float cw2v = svec[192 + jb + 2], cw3 = svec[192 + jb + 3];
            float p[3];
#pragma unroll
            for (int i = 0; i < 3; i++) {
                float c0, c1, c2, c3;
                unpack2(acc[i][0], c0, c1); unpack2(acc[i][1], c2, c3);
                p[i] = silu_f(c0) * cw0 + silu_f(c1) * cw1v +
                       silu_f(c2) * cw2v + silu_f(c3) * cw3;
            }
#pragma unroll
            for (int o = 1; o < 16; o <<= 1) {
#pragma unroll
                for (int i = 0; i < 3; i++)
                    p[i] += __shfl_xor_sync(0xffffffffu, p[i], o);
            }
            if (tx == 0) {
#pragma unroll
                for (int i = 0; i < 3; i++) sSv[wid][th * 3 + i] = p[i];
            }
        }
        __syncwarp();   // sSv ready; actw(m) still valid

        // ---- stage 5: vectorized reduction aggregation (red.global.add.v4) ----
#pragma unroll
        for (int q = 0; q < 3; q++) {
            int idx = lane + 32 * q;        // 0..95 covers EW(6)*16 v4-chunks
            int el = idx >> 4, jg = (idx & 15) * 4;
            if (base + el < E) {
                float4 v = *(const float4*)(actw + el * 64 + jg);
                red_add_v4(g_agg + sRow[wid][el] * 64 + jg, v);
            }
        }
        if (lane < EW * 3) {
            int el = lane / 3, d = lane - el * 3;
            if (base + el < E)
                atomicAdd(&g_trans[sRow[wid][el] * 3 + d], sDiff[wid][el][d] * sSv[wid][el]);
        }
        __syncwarp();   // buffers consumed before next chunk overwrites
    }
}

// ---------- fused node update + next-layer precompute (layers 0..2) ----------
__global__ void __launch_bounds__(256) k_node_fused(
    const float* __restrict__ W1, const float* __restrict__ b1,     // node mlp
    const float* __restrict__ W2, const float* __restrict__ b2,
    const float* __restrict__ eW1, const float* __restrict__ eb1,   // next layer edge [129][64]
    int n) {
    __shared__ __align__(16) char smem[49152];
    float2 (*sW1)[32] = (float2(*)[32])smem;             // [128][32] = 32KB
    float2 (*sW2)[32] = (float2(*)[32])(smem + 32768);   // [64][32]  = 16KB
    int tid = threadIdx.x;
    for (int idx = tid; idx < 128 * 32; idx += 256) {
        int k = idx >> 5, j = idx & 31;
        sW1[k][j] = make_float2(W1[k * 64 + j], W1[k * 64 + j + 32]);
    }
    for (int idx = tid; idx < 64 * 32; idx += 256) {
        int k = idx >> 5, j = idx & 31;
        sW2[k][j] = make_float2(W2[k * 64 + j], W2[k * 64 + j + 32]);
    }
    __syncthreads();
    int warp = tid >> 5, lane = tid & 31;
    int i = blockIdx.x * 8 + warp;
    bool act = (i < n);

    float h0 = 0.f, h1 = 0.f;
    if (act) {
        if (lane < 3) {
            float cnt = fmaxf(g_cnt[i], 1.0f);
            g_x[i * 3 + lane] += g_trans[i * 3 + lane] / cnt;
        }
        h0 = g_h[i * 64 + lane];
        h1 = g_h[i * 64 + 32 + lane];
        float a0 = g_agg[i * 64 + lane], a1 = g_agg[i * 64 + 32 + lane];
        float t0 = __ldg(b1 + lane), t1 = __ldg(b1 + lane + 32);
#pragma unroll
        for (int k = 0; k < 128; k++) {
            float v;
            if (k < 32)       v = __shfl_sync(0xffffffffu, h0, k);
            else if (k < 64)  v = __shfl_sync(0xffffffffu, h1, k - 32);
            else if (k < 96)  v = __shfl_sync(0xffffffffu, a0, k - 64);
            else              v = __shfl_sync(0xffffffffu, a1, k - 96);
            float2 w = sW1[k][lane];
            t0 += v * w.x;
            t1 += v * w.y;
        }
        t0 = silu_f(t0);
        t1 = silu_f(t1);
        float o0 = __ldg(b2 + lane), o1 = __ldg(b2 + lane + 32);
#pragma unroll
        for (int k = 0; k < 64; k++) {
            float v = (k < 32) ? __shfl_sync(0xffffffffu, t0, k)
                               : __shfl_sync(0xffffffffu, t1, k - 32);
            float2 w = sW2[k][lane];
            o0 += v * w.x;
            o1 += v * w.y;
        }
        h0 += o0;
        h1 += o1;
        g_h[i * 64 + lane] = h0;
        g_h[i * 64 + 32 + lane] = h1;
    }
    __syncthreads();  // phase A shared reads complete -> overlay

    float2 (*sWa)[32] = (float2(*)[32])smem;             // [64][32] = 16KB
    float2 (*sWb)[32] = (float2(*)[32])(smem + 16384);   // [64][32] = 16KB
    for (int idx = tid; idx < 64 * 32; idx += 256) {
        int k = idx >> 5, j = idx & 31;
        sWa[k][j] = make_float2(eW1[k * 64 + j], eW1[k * 64 + j + 32]);
        sWb[k][j] = make_float2(eW1[(k + 64) * 64 + j], eW1[(k + 64) * 64 + j + 32]);
    }
    __syncthreads();

    if (act) {
        float a0 = __ldg(eb1 + lane), a1 = __ldg(eb1 + lane + 32);  // fold edge b1 into Pa
        float c0 = 0.f, c1 = 0.f;
#pragma unroll
        for (int k = 0; k < 64; k++) {
            float v = (k < 32) ? __shfl_sync(0xffffffffu, h0, k)
                               : __shfl_sync(0xffffffffu, h1, k - 32);
            float2 wa = sWa[k][lane];
            float2 wb = sWb[k][lane];
            a0 += v * wa.x; a1 += v * wa.y;
            c0 += v * wb.x; c1 += v * wb.y;
        }
        g_Pa[i * 64 + lane] = a0;
        g_Pa[i * 64 + 32 + lane] = a1;
        g_Pb[i * 64 + lane] = c0;
        g_Pb[i * 64 + 32 + lane] = c1;
        g_agg[i * 64 + lane] = 0.f;
        g_agg[i * 64 + 32 + lane] = 0.f;
        if (lane < 3) g_trans[i * 3 + lane] = 0.f;
    }
}

// ---------- fused LAST node update + embedding_out + head (layer 3) ----------
__global__ void __launch_bounds__(256) k_node_last(
    const float* __restrict__ W1, const float* __restrict__ b1,     // node mlp
    const float* __restrict__ W2, const float* __restrict__ b2,
    const float* __restrict__ We, const float* __restrict__ be,     // emb_out
    const float* __restrict__ Hw1, const float* __restrict__ hb1,   // head
    const float* __restrict__ Hw2, const float* __restrict__ hb2,
    float* __restrict__ out, int n) {
    __shared__ __align__(16) char smem[49152];
    int tid = threadIdx.x;
    int warp = tid >> 5, lane = tid & 31;
    int i = blockIdx.x * 8 + warp;
    bool act = (i < n);

    {
        float2 (*sW1)[32] = (float2(*)[32])smem;
        float2 (*sW2)[32] = (float2(*)[32])(smem + 32768);
        for (int idx = tid; idx < 128 * 32; idx += 256) {
            int k = idx >> 5, j = idx & 31;
            sW1[k][j] = make_float2(W1[k * 64 + j], W1[k * 64 + j + 32]);
        }
        for (int idx = tid; idx < 64 * 32; idx += 256) {
            int k = idx >> 5, j = idx & 31;
            sW2[k][j] = make_float2(W2[k * 64 + j], W2[k * 64 + j + 32]);
        }
        __syncthreads();

        float h0 = 0.f, h1 = 0.f;
        if (act) {
            if (lane < 3) {
                float cnt = fmaxf(g_cnt[i], 1.0f);
                g_x[i * 3 + lane] += g_trans[i * 3 + lane] / cnt;
            }
            h0 = g_h[i * 64 + lane];
            h1 = g_h[i * 64 + 32 + lane];
            float a0 = g_agg[i * 64 + lane], a1 = g_agg[i * 64 + 32 + lane];
            float t0 = __ldg(b1 + lane), t1 = __ldg(b1 + lane + 32);
#pragma unroll
            for (int k = 0; k < 128; k++) {
                float v;
                if (k < 32)       v = __shfl_sync(0xffffffffu, h0, k);
                else if (k < 64)  v = __shfl_sync(0xffffffffu, h1, k - 32);
                else if (k < 96)  v = __shfl_sync(0xffffffffu, a0, k - 64);
                else              v = __shfl_sync(0xffffffffu, a1, k - 96);
                float2 w = sW1[k][lane];
                t0 += v * w.x;
                t1 += v * w.y;
            }
            t0 = silu_f(t0);
            t1 = silu_f(t1);
            float o0 = __ldg(b2 + lane), o1 = __ldg(b2 + lane + 32);
#pragma unroll
            for (int k = 0; k < 64; k++) {
                float v = (k < 32) ? __shfl_sync(0xffffffffu, t0, k)
                                   : __shfl_sync(0xffffffffu, t1, k - 32);
                float2 w = sW2[k][lane];
                o0 += v * w.x;
                o1 += v * w.y;
            }
            h0 += o0;
            h1 += o1;
        }
        __syncthreads();  // phase A shared reads complete -> overlay

        float2 (*sWe)[32] = (float2(*)[32])smem;
        float2 (*sH1)[32] = (float2(*)[32])(smem + 16384);
        float  (*sH2)[20] = (float(*)[20])(smem + 32768);
        float* sbe  = (float*)(smem + 32768 + 5120);
        float* shb1 = sbe + 64;
        float* shb2 = shb1 + 64;
        for (int idx = tid; idx < 64 * 32; idx += 256) {
            int k = idx >> 5, j = idx & 31;
            sWe[k][j] = make_float2(We[k * 64 + j], We[k * 64 + j + 32]);
            sH1[k][j] = make_float2(Hw1[k * 64 + j], Hw1[k * 64 + j + 32]);
        }
        for (int idx = tid; idx < 64 * 20; idx += 256) sH2[idx / 20][idx % 20] = Hw2[idx];
        if (tid < 64) { sbe[tid] = be[tid]; shb1[tid] = hb1[tid]; }
        if (tid >= 64 && tid < 84) shb2[tid - 64] = hb2[tid - 64];
        __syncthreads();

        if (act) {
            float e0 = sbe[lane], e1 = sbe[lane + 32];
#pragma unroll
            for (int k = 0; k < 64; k++) {
                float v = (k < 32) ? __shfl_sync(0xffffffffu, h0, k)
                                   : __shfl_sync(0xffffffffu, h1, k - 32);
                float2 w = sWe[k][lane];
                e0 += v * w.x;
                e1 += v * w.y;
            }
            float t0 = shb1[lane], t1 = shb1[lane + 32];
#pragma unroll
            for (int k = 0; k < 64; k++) {
                float v = (k < 32) ? __shfl_sync(0xffffffffu, e0, k)
                                   : __shfl_sync(0xffffffffu, e1, k - 32);
                float2 w = sH1[k][lane];
                t0 += v * w.x;
                t1 += v * w.y;
            }
            t0 = fmaxf(t0, 0.f);
            t1 = fmaxf(t1, 0.f);
            int jo = (lane < 20) ? lane : 0;
            float o = (lane < 20) ? shb2[lane] : 0.f;
#pragma unroll
            for (int k = 0; k < 64; k++) {
                float v = (k < 32) ? __shfl_sync(0xffffffffu, t0, k)
                                   : __shfl_sync(0xffffffffu, t1, k - 32);
                o += v * sH2[k][jo];
            }
            if (lane < 20) out[i * 20 + lane] = o;
        }
    }
}

extern "C" void kernel_launch(void* const* d_in, const int* in_sizes, int n_in,
                              void* d_out, int out_size) {
    const float* h         = (const float*)d_in[0];
    const float* x         = (const float*)d_in[1];
    const int*   edges     = (const int*)d_in[2];
    const float* emb_in_w  = (const float*)d_in[3];
    const float* emb_in_b  = (const float*)d_in[4];
    const float* emb_out_w = (const float*)d_in[5];
    const float* emb_out_b = (const float*)d_in[6];
    const float* edge_w1   = (const float*)d_in[7];
    const float* edge_b1   = (const float*)d_in[8];
    const float* edge_w2   = (const float*)d_in[9];
    const float* edge_b2   = (const float*)d_in[10];
    const float* node_w1   = (const float*)d_in[11];
    const float* node_b1   = (const float*)d_in[12];
    const float* node_w2   = (const float*)d_in[13];
    const float* node_b2   = (const float*)d_in[14];
    const float* coord_w1  = (const float*)d_in[15];
    const float* coord_b1  = (const float*)d_in[16];
    const float* coord_w2  = (const float*)d_in[17];
    const float* head_w1   = (const float*)d_in[18];
    const float* head_b1   = (const float*)d_in[19];
    const float* head_w2   = (const float*)d_in[20];
    const float* head_b2   = (const float*)d_in[21];
    float* out = (float*)d_out;

    int n = in_sizes[0] / 21;
    int E = in_sizes[2] / 2;
    const int* row = edges;
    const int* col = edges + E;

    int nb  = (n + 255) / 256;
    int nwb = (n + 7) / 8;              // warp-per-node blocks (8 warps/block)
    int nChunks = (E + EW - 1) / EW;    // warp-chunks of EW edges
    int egrid = 592;                    // 148 SMs * 4 CTAs (smem-bound)
    if (egrid * 8 > nChunks) egrid = (nChunks + 7) / 8;

    k_init<<<nb, 256>>>(x, n);
    k_cnt<<<(E + 255) / 256, 256>>>(row, E);
    k_embed<<<nwb, 256>>>(h, emb_in_w, emb_in_b, n);
    k_node_pre<<<nwb, 256>>>(edge_w1, edge_b1, n);   // layer 0 Pa/Pb

    for (int l = 0; l < 4; l++) {
        k_edge<<<egrid, 256>>>(row, col,
                               edge_w1 + l * 129 * 64 + 128 * 64,
                               edge_w2 + l * 4096, edge_b2 + l * 64,
                               coord_w1 + l * 4096, coord_b1 + l * 64,
                               coord_w2 + l * 64, E, nChunks);
        if (l < 3) {
            k_node_fused<<<nwb, 256>>>(node_w1 + l * 128 * 64, node_b1 + l * 64,
                                       node_w2 + l * 4096, node_b2 + l * 64,
                                       edge_w1 + (l + 1) * 129 * 64,
                                       edge_b1 + (l + 1) * 64, n);
        } else {
            k_node_last<<<nwb, 256>>>(node_w1 + l * 128 * 64, node_b1 + l * 64,
                                      node_w2 + l * 4096, node_b2 + l * 64,
                                      emb_out_w, emb_out_b,
                                      head_w1, head_b1, head_w2, head_b2,
                                      out, n);
        }
    }
}

// round 16
// speedup vs baseline: 1.1782x; 1.0029x over previous
#include <cuda_runtime.h>

#define NMAX 50000
#define EMAX 800000
#define HID 64
#define EW 6   // edges per warp-chunk in edge kernel

// ---------- scratch (device globals; no allocation allowed) ----------
__device__ float g_h[NMAX * HID];
__device__ float4 g_x4[NMAX];        // xyz padded to float4 (one LDG.128 per node)
__device__ float g_Pa[NMAX * HID];   // h @ W1a + b1  (gathered at row)
__device__ float g_Pb[NMAX * HID];   // h @ W1b       (gathered at col)
__device__ float g_agg[NMAX * HID];  // segment_sum of m
__device__ float g_trans[NMAX * 3];  // segment_sum of diff * s
__device__ float g_cnt[NMAX];

__device__ __forceinline__ float silu_f(float v) {
    return v * (1.0f / (1.0f + __expf(-v)));
}

__device__ __forceinline__ unsigned long long pack2(float lo, float hi) {
    unsigned long long r;
    asm("mov.b64 %0, {%1, %2};" : "=l"(r) : "r"(__float_as_uint(lo)), "r"(__float_as_uint(hi)));
    return r;
}
__device__ __forceinline__ unsigned long long bcast2(float v) {
    unsigned long long r;
    unsigned u = __float_as_uint(v);
    asm("mov.b64 %0, {%1, %1};" : "=l"(r) : "r"(u));
    return r;
}
__device__ __forceinline__ void unpack2(unsigned long long p, float& lo, float& hi) {
    unsigned a, b;
    asm("mov.b64 {%0, %1}, %2;" : "=r"(a), "=r"(b) : "l"(p));
    lo = __uint_as_float(a);
    hi = __uint_as_float(b);
}
__device__ __forceinline__ void fma2(unsigned long long& acc, unsigned long long a,
                                     unsigned long long b) {
    asm volatile("fma.rn.f32x2 %0, %1, %2, %0;" : "+l"(acc) : "l"(a), "l"(b));
}
// 16-byte shared load as two packed f32x2 operands
__device__ __forceinline__ void lds_v2u64(unsigned addr, unsigned long long& w01,
                                          unsigned long long& w23) {
    asm volatile("ld.shared.v2.u64 {%0, %1}, [%2];" : "=l"(w01), "=l"(w23) : "r"(addr));
}
// vectorized no-return global reduction (sm_90+); explicit global-space address
__device__ __forceinline__ void red_add_v4(float* ptr, float4 v) {
    unsigned long long gaddr = __cvta_generic_to_global(ptr);
    asm volatile("red.global.add.v4.f32 [%0], {%1, %2, %3, %4};"
                 :: "l"(gaddr), "f"(v.x), "f"(v.y), "f"(v.z), "f"(v.w) : "memory");
}

// ---------- init: zero cnt, copy x into padded working buffer ----------
__global__ void __launch_bounds__(256) k_init(const float* __restrict__ x, int n) {
    int i = blockIdx.x * blockDim.x + threadIdx.x;
    if (i < n) {
        g_cnt[i] = 0.f;
        g_x4[i] = make_float4(x[i * 3 + 0], x[i * 3 + 1], x[i * 3 + 2], 0.f);
    }
}

// ---------- in-degree count ----------
__global__ void __launch_bounds__(256) k_cnt(const int* __restrict__ row, int E) {
    int e = blockIdx.x * blockDim.x + threadIdx.x;
    if (e < E) atomicAdd(&g_cnt[row[e]], 1.0f);
}

// ---------- embedding_in: g_h = h @ W[21,64] + b ----------
__global__ void __launch_bounds__(256) k_embed(const float* __restrict__ h,
                                               const float* __restrict__ W,
                                               const float* __restrict__ b, int n) {
    __shared__ float sW[21][64];
    __shared__ float sb[64];
    int tid = threadIdx.x;
    for (int idx = tid; idx < 21 * 64; idx += 256) sW[idx / 64][idx % 64] = W[idx];
    if (tid < 64) sb[tid] = b[tid];
    __syncthreads();
    int warp = tid >> 5, lane = tid & 31;
    int i = blockIdx.x * 8 + warp;
    if (i >= n) return;
    float hv = (lane < 21) ? h[i * 21 + lane] : 0.f;
    float a0 = sb[lane], a1 = sb[lane + 32];
#pragma unroll
    for (int k = 0; k < 21; k++) {
        float v = __shfl_sync(0xffffffffu, hv, k);
        a0 += v * sW[k][lane];
        a1 += v * sW[k][lane + 32];
    }
    g_h[i * 64 + lane] = a0;
    g_h[i * 64 + 32 + lane] = a1;
}

// ---------- standalone node precompute (layer 0): Pa/Pb from g_h; zero agg/trans ----------
__global__ void __launch_bounds__(256) k_node_pre(const float* __restrict__ W1,  // [129][64]
                                                  const float* __restrict__ b1, int n) {
    __shared__ float2 sWa[64][32];
    __shared__ float2 sWb[64][32];
    __shared__ float sb1[64];
    int tid = threadIdx.x;
    for (int idx = tid; idx < 64 * 32; idx += 256) {
        int k = idx >> 5, j = idx & 31;
        sWa[k][j] = make_float2(W1[k * 64 + j], W1[k * 64 + j + 32]);
        sWb[k][j] = make_float2(W1[(k + 64) * 64 + j], W1[(k + 64) * 64 + j + 32]);
    }
    if (tid < 64) sb1[tid] = b1[tid];
    __syncthreads();
    int warp = tid >> 5, lane = tid & 31;
    int i = blockIdx.x * 8 + warp;
    if (i >= n) return;
    float h0 = g_h[i * 64 + lane], h1 = g_h[i * 64 + 32 + lane];
    float a0 = sb1[lane], a1 = sb1[lane + 32];   // fold edge bias b1 into Pa
    float c0 = 0.f, c1 = 0.f;
#pragma unroll
    for (int k = 0; k < 64; k++) {
        float v = (k < 32) ? __shfl_sync(0xffffffffu, h0, k)
                           : __shfl_sync(0xffffffffu, h1, k - 32);
        float2 wa = sWa[k][lane];
        float2 wb = sWb[k][lane];
        a0 += v * wa.x; a1 += v * wa.y;
        c0 += v * wb.x; c1 += v * wb.y;
    }
    g_Pa[i * 64 + lane] = a0;
    g_Pa[i * 64 + 32 + lane] = a1;
    g_Pb[i * 64 + lane] = c0;
    g_Pb[i * 64 + 32 + lane] = c1;
    g_agg[i * 64 + lane] = 0.f;
    g_agg[i * 64 + 32 + lane] = 0.f;
    if (lane < 3) g_trans[i * 3 + lane] = 0.f;
}

// ---------- warp-autonomous edge kernel: each warp owns EW edges end-to-end ----------
// No CTA barriers in the main loop; per-warp activation buffer + __syncwarp only.
__global__ void __launch_bounds__(256) k_edge(
    const int* __restrict__ row, const int* __restrict__ col,
    const float* __restrict__ w1c,               // [64] radial row of edge_w1
    const float* __restrict__ W2, const float* __restrict__ b2,
    const float* __restrict__ Cw1, const float* __restrict__ cb1,
    const float* __restrict__ Cw2, int E, int nChunks) {
    __shared__ __align__(16) float sW2[64 * 64];      // 16KB
    __shared__ __align__(16) float sC1[64 * 64];      // 16KB
    __shared__ __align__(16) float sAct[8][EW * 64];  // 12KB (per-warp)
    __shared__ int   sRow[8][EW];
    __shared__ float sDiff[8][EW][3];
    __shared__ float sSv[8][EW];
    __shared__ float svec[256];                       // [w1c | b2 | cb1 | Cw2]

    int tid = threadIdx.x, wid = tid >> 5, lane = tid & 31;
    // ---- one-time weight staging (only CTA barrier in the kernel) ----
    for (int idx = tid; idx < 1024; idx += 256) {
        ((float4*)sW2)[idx] = ((const float4*)W2)[idx];
        ((float4*)sC1)[idx] = ((const float4*)Cw1)[idx];
    }
    if (tid < 64)       svec[tid] = w1c[tid];
    else if (tid < 128) svec[tid] = b2[tid - 64];
    else if (tid < 192) svec[tid] = cb1[tid - 128];
    else                svec[tid] = Cw2[tid - 192];
    __syncthreads();

    int tx = lane & 15, th = lane >> 4;   // 16 col-lanes x 2 half-warps
    int jb = tx * 4;
    float* actw = sAct[wid];
    unsigned sW2a = (unsigned)__cvta_generic_to_shared(sW2) + jb * 4;
    unsigned sC1a = (unsigned)__cvta_generic_to_shared(sC1) + jb * 4;

    int gw = blockIdx.x * 8 + wid;       // global warp id
    int wstride = gridDim.x * 8;

    // ---- index prefetch for the first chunk (r = -1 marks invalid edge) ----
    int pr[3], pc[3];
#pragma unroll
    for (int i = 0; i < 3; i++) { pr[i] = -1; pc[i] = 0; }
    if (gw < nChunks) {
#pragma unroll
        for (int i = 0; i < 3; i++) {
            int ge = gw * EW + th * 3 + i;
            if (ge < E) { pr[i] = row[ge]; pc[i] = col[ge]; }
        }
    }

    for (int ch = gw; ch < nChunks; ch += wstride) {
        int base = ch * EW;
        int cr[3] = {pr[0], pr[1], pr[2]}, cc[3] = {pc[0], pc[1], pc[2]};

        // ---- stage 1: m1 = silu(Pa[r] + Pb[c] + radial * w1c) -> actw ----
#pragma unroll
        for (int i = 0; i < 3; i++) {
            int el = th * 3 + i;
            int r = cr[i], c = cc[i];
            float4 res;
            if (r >= 0) {
                float4 pa = *(const float4*)(g_Pa + r * 64 + jb);
                float4 pb = *(const float4*)(g_Pb + c * 64 + jb);
                float4 xr = g_x4[r];
                float4 xc = g_x4[c];
                float dx = xr.x - xc.x;
                float dy = xr.y - xc.y;
                float dz = xr.z - xc.z;
                float rad = dx * dx + dy * dy + dz * dz;
                if (tx == 0) {
                    sRow[wid][el] = r;
                    sDiff[wid][el][0] = dx; sDiff[wid][el][1] = dy; sDiff[wid][el][2] = dz;
                }
                res.x = silu_f(pa.x + pb.x + rad * svec[jb + 0]);
                res.y = silu_f(pa.y + pb.y + rad * svec[jb + 1]);
                res.z = silu_f(pa.z + pb.z + rad * svec[jb + 2]);
                res.w = silu_f(pa.w + pb.w + rad * svec[jb + 3]);
            } else {
                if (tx == 0) {
                    sRow[wid][el] = 0;
                    sDiff[wid][el][0] = sDiff[wid][el][1] = sDiff[wid][el][2] = 0.f;
                }
                res = make_float4(0.f, 0.f, 0.f, 0.f);
            }
            ((float4*)(actw + el * 64))[tx] = res;
        }
        // prefetch next chunk's indices (latency hidden behind stages 2-5)
        pr[0] = pr[1] = pr[2] = -1;
        {
            int cn = ch + wstride;
            if (cn < nChunks) {
#pragma unroll
                for (int i = 0; i < 3; i++) {
                    int ge = cn * EW + th * 3 + i;
                    if (ge < E) { pr[i] = row[ge]; pc[i] = col[ge]; }
                }
            }
        }
        __syncwarp();   // actw = m1 ready; meta ready

        // ---- stage 2: m = silu(m1 @ W2 + b2), acc in regs (packed f32x2) ----
        unsigned long long acc[3][2];
        {
            unsigned long long bias01 = pack2(svec[64 + jb], svec[64 + jb + 1]);
            unsigned long long bias23 = pack2(svec[64 + jb + 2], svec[64 + jb + 3]);
#pragma unroll
            for (int i = 0; i < 3; i++) { acc[i][0] = bias01; acc[i][1] = bias23; }
            const float4* av0 = (const float4*)(actw + (th * 3 + 0) * 64);
            const float4* av1 = (const float4*)(actw + (th * 3 + 1) * 64);
            const float4* av2 = (const float4*)(actw + (th * 3 + 2) * 64);
#pragma unroll 4
            for (int kb = 0; kb < 16; kb++) {
                float4 a0 = av0[kb], a1 = av1[kb], a2 = av2[kb];
                const float* p0 = (const float*)&a0;
                const float* p1 = (const float*)&a1;
                const float* p2 = (const float*)&a2;
#pragma unroll
                for (int kk = 0; kk < 4; kk++) {
                    unsigned long long w01, w23;
                    lds_v2u64(sW2a + (unsigned)((kb * 4 + kk) * 256), w01, w23);
                    unsigned long long b0 = bcast2(p0[kk]);
                    unsigned long long b1 = bcast2(p1[kk]);
                    unsigned long long b2v = bcast2(p2[kk]);
                    fma2(acc[0][0], b0, w01); fma2(acc[0][1], b0, w23);
                    fma2(acc[1][0], b1, w01); fma2(acc[1][1], b1, w23);
                    fma2(acc[2][0], b2v, w01); fma2(acc[2][1], b2v, w23);
                }
            }
        }
        __syncwarp();   // all reads of m1 done -> actw reusable
#pragma unroll
        for (int i = 0; i < 3; i++) {
            float v0, v1, v2, v3;
            unpack2(acc[i][0], v0, v1); unpack2(acc[i][1], v2, v3);
            ((float4*)(actw + (th * 3 + i) * 64))[tx] =
                make_float4(silu_f(v0), silu_f(v1), silu_f(v2), silu_f(v3));
        }
        __syncwarp();   // actw = m ready

        // ---- stage 3+4: cmid = silu(m @ Cw1 + cb1); s = cmid . Cw2 ----
        {
            unsigned long long bias01 = pack2(svec[128 + jb], svec[128 + jb + 1]);
            unsigned long long bias23 = pack2(svec[128 + jb + 2], svec[128 + jb + 3]);
#pragma unroll
            for (int i = 0; i < 3; i++) { acc[i][0] = bias01; acc[i][1] = bias23; }
            const float4* av0 = (const float4*)(actw + (th * 3 + 0) * 64);
            const float4* av1 = (const float4*)(actw + (th * 3 + 1) * 64);
            const float4* av2 = (const float4*)(actw + (th * 3 + 2) * 64);
#pragma unroll 4
            for (int kb = 0; kb < 16; kb++) {
                float4 a0 = av0[kb], a1 = av1[kb], a2 = av2[kb];
                const float* p0 = (const float*)&a0;
                const float* p1 = (const float*)&a1;
                const float* p2 = (const float*)&a2;
#pragma unroll
                for (int kk = 0; kk < 4; kk++) {
                    unsigned long long w01, w23;
                    lds_v2u64(sC1a + (unsigned)((kb * 4 + kk) * 256), w01, w23);
                    unsigned long long b0 = bcast2(p0[kk]);
                    unsigned long long b1 = bcast2(p1[kk]);
                    unsigned long long b2v = bcast2(p2[kk]);
                    fma2(acc[0][0], b0, w01); fma2(acc[0][1], b0, w23);
                    fma2(acc[1][0], b1, w01); fma2(acc[1][1], b1, w23);
                    fma2(acc[2][0], b2v, w01); fma2(acc[2][1], b2v, w23);
                }
            }
            float cw0 = svec[192 + jb], cw1v = svec[192 + jb + 1];
            float cw2v = svec[192 + jb + 2], cw3 = svec[192 + jb + 3];
            float p[3];
#pragma unroll
            for (int i = 0; i < 3; i++) {
                float c0, c1, c2, c3;
                unpack2(acc[i][0], c0, c1); unpack2(acc[i][1], c2, c3);
                p[i] = silu_f(c0) * cw0 + silu_f(c1) * cw1v +
                       silu_f(c2) * cw2v + silu_f(c3) * cw3;
            }
#pragma unroll
            for (int o = 1; o < 16; o <<= 1) {
#pragma unroll
                for (int i = 0; i < 3; i++)
                    p[i] += __shfl_xor_sync(0xffffffffu, p[i], o);
            }
            if (tx == 0) {
#pragma unroll
                for (int i = 0; i < 3; i++) sSv[wid][th * 3 + i] = p[i];
            }
        }
        __syncwarp();   // sSv ready; actw(m) still valid

        // ---- stage 5: vectorized reduction aggregation (red.global.add.v4) ----
#pragma unroll
        for (int q = 0; q < 3; q++) {
            int idx = lane + 32 * q;        // 0..95 covers EW(6)*16 v4-chunks
            int el = idx >> 4, jg = (idx & 15) * 4;
            if (base + el < E) {
                float4 v = *(const float4*)(actw + el * 64 + jg);
                red_add_v4(g_agg + sRow[wid][el] * 64 + jg, v);
            }
        }
        if (lane < EW * 3) {
            int el = lane / 3, d = lane - el * 3;
            if (base + el < E)
                atomicAdd(&g_trans[sRow[wid][el] * 3 + d], sDiff[wid][el][d] * sSv[wid][el]);
        }
        __syncwarp();   // buffers consumed before next chunk overwrites
    }
}

// ---------- fused node update + next-layer precompute (layers 0..2) ----------
__global__ void __launch_bounds__(256) k_node_fused(
    const float* __restrict__ W1, const float* __restrict__ b1,     // node mlp
    const float* __restrict__ W2, const float* __restrict__ b2,
    const float* __restrict__ eW1, const float* __restrict__ eb1,   // next layer edge [129][64]
    int n) {
    __shared__ __align__(16) char smem[49152];
    float2 (*sW1)[32] = (float2(*)[32])smem;             // [128][32] = 32KB
    float2 (*sW2)[32] = (float2(*)[32])(smem + 32768);   // [64][32]  = 16KB
    int tid = threadIdx.x;
    for (int idx = tid; idx < 128 * 32; idx += 256) {
        int k = idx >> 5, j = idx & 31;
        sW1[k][j] = make_float2(W1[k * 64 + j], W1[k * 64 + j + 32]);
    }
    for (int idx = tid; idx < 64 * 32; idx += 256) {
        int k = idx >> 5, j = idx & 31;
        sW2[k][j] = make_float2(W2[k * 64 + j], W2[k * 64 + j + 32]);
    }
    __syncthreads();
    int warp = tid >> 5, lane = tid & 31;
    int i = blockIdx.x * 8 + warp;
    bool act = (i < n);

    float h0 = 0.f, h1 = 0.f;
    if (act) {
        if (lane < 3) {
            float cnt = fmaxf(g_cnt[i], 1.0f);
            ((float*)&g_x4[i])[lane] += g_trans[i * 3 + lane] / cnt;
        }
        h0 = g_h[i * 64 + lane];
        h1 = g_h[i * 64 + 32 + lane];
        float a0 = g_agg[i * 64 + lane], a1 = g_agg[i * 64 + 32 + lane];
        float t0 = __ldg(b1 + lane), t1 = __ldg(b1 + lane + 32);
#pragma unroll
        for (int k = 0; k < 128; k++) {
            float v;
            if (k < 32)       v = __shfl_sync(0xffffffffu, h0, k);
            else if (k < 64)  v = __shfl_sync(0xffffffffu, h1, k - 32);
            else if (k < 96)  v = __shfl_sync(0xffffffffu, a0, k - 64);
            else              v = __shfl_sync(0xffffffffu, a1, k - 96);
            float2 w = sW1[k][lane];
            t0 += v * w.x;
            t1 += v * w.y;
        }
        t0 = silu_f(t0);
        t1 = silu_f(t1);
        float o0 = __ldg(b2 + lane), o1 = __ldg(b2 + lane + 32);
#pragma unroll
        for (int k = 0; k < 64; k++) {
            float v = (k < 32) ? __shfl_sync(0xffffffffu, t0, k)
                               : __shfl_sync(0xffffffffu, t1, k - 32);
            float2 w = sW2[k][lane];
            o0 += v * w.x;
            o1 += v * w.y;
        }
        h0 += o0;
        h1 += o1;
        g_h[i * 64 + lane] = h0;
        g_h[i * 64 + 32 + lane] = h1;
    }
    __syncthreads();  // phase A shared reads complete -> overlay

    float2 (*sWa)[32] = (float2(*)[32])smem;             // [64][32] = 16KB
    float2 (*sWb)[32] = (float2(*)[32])(smem + 16384);   // [64][32] = 16KB
    for (int idx = tid; idx < 64 * 32; idx += 256) {
        int k = idx >> 5, j = idx & 31;
        sWa[k][j] = make_float2(eW1[k * 64 + j], eW1[k * 64 + j + 32]);
        sWb[k][j] = make_float2(eW1[(k + 64) * 64 + j], eW1[(k + 64) * 64 + j + 32]);
    }
    __syncthreads();

    if (act) {
        float a0 = __ldg(eb1 + lane), a1 = __ldg(eb1 + lane + 32);  // fold edge b1 into Pa
        float c0 = 0.f, c1 = 0.f;
#pragma unroll
        for (int k = 0; k < 64; k++) {
            float v = (k < 32) ? __shfl_sync(0xffffffffu, h0, k)
                               : __shfl_sync(0xffffffffu, h1, k - 32);
            float2 wa = sWa[k][lane];
            float2 wb = sWb[k][lane];
            a0 += v * wa.x; a1 += v * wa.y;
            c0 += v * wb.x; c1 += v * wb.y;
        }
        g_Pa[i * 64 + lane] = a0;
        g_Pa[i * 64 + 32 + lane] = a1;
        g_Pb[i * 64 + lane] = c0;
        g_Pb[i * 64 + 32 + lane] = c1;
        g_agg[i * 64 + lane] = 0.f;
        g_agg[i * 64 + 32 + lane] = 0.f;
        if (lane < 3) g_trans[i * 3 + lane] = 0.f;
    }
}

// ---------- fused LAST node update + embedding_out + head (layer 3) ----------
__global__ void __launch_bounds__(256) k_node_last(
    const float* __restrict__ W1, const float* __restrict__ b1,     // node mlp
    const float* __restrict__ W2, const float* __restrict__ b2,
    const float* __restrict__ We, const float* __restrict__ be,     // emb_out
    const float* __restrict__ Hw1, const float* __restrict__ hb1,   // head
    const float* __restrict__ Hw2, const float* __restrict__ hb2,
    float* __restrict__ out, int n) {
    __shared__ __align__(16) char smem[49152];
    int tid = threadIdx.x;
    int warp = tid >> 5, lane = tid & 31;
    int i = blockIdx.x * 8 + warp;
    bool act = (i < n);

    {
        float2 (*sW1)[32] = (float2(*)[32])smem;
        float2 (*sW2)[32] = (float2(*)[32])(smem + 32768);
        for (int idx = tid; idx < 128 * 32; idx += 256) {
            int k = idx >> 5, j = idx & 31;
            sW1[k][j] = make_float2(W1[k * 64 + j], W1[k * 64 + j + 32]);
        }
        for (int idx = tid; idx < 64 * 32; idx += 256) {
            int k = idx >> 5, j = idx & 31;
            sW2[k][j] = make_float2(W2[k * 64 + j], W2[k * 64 + j + 32]);
        }
        __syncthreads();

        float h0 = 0.f, h1 = 0.f;
        if (act) {
            if (lane < 3) {
                float cnt = fmaxf(g_cnt[i], 1.0f);
                ((float*)&g_x4[i])[lane] += g_trans[i * 3 + lane] / cnt;
            }
            h0 = g_h[i * 64 + lane];
            h1 = g_h[i * 64 + 32 + lane];
            float a0 = g_agg[i * 64 + lane], a1 = g_agg[i * 64 + 32 + lane];
            float t0 = __ldg(b1 + lane), t1 = __ldg(b1 + lane + 32);
#pragma unroll
            for (int k = 0; k < 128; k++) {
                float v;
                if (k < 32)       v = __shfl_sync(0xffffffffu, h0, k);
                else if (k < 64)  v = __shfl_sync(0xffffffffu, h1, k - 32);
                else if (k < 96)  v = __shfl_sync(0xffffffffu, a0, k - 64);
                else              v = __shfl_sync(0xffffffffu, a1, k - 96);
                float2 w = sW1[k][lane];
                t0 += v * w.x;
                t1 += v * w.y;
            }
            t0 = silu_f(t0);
            t1 = silu_f(t1);
            float o0 = __ldg(b2 + lane), o1 = __ldg(b2 + lane + 32);
#pragma unroll
            for (int k = 0; k < 64; k++) {
                float v = (k < 32) ? __shfl_sync(0xffffffffu, t0, k)
                                   : __shfl_sync(0xffffffffu, t1, k - 32);
                float2 w = sW2[k][lane];
                o0 += v * w.x;
                o1 += v * w.y;
            }
            h0 += o0;
            h1 += o1;
        }
        __syncthreads();  // phase A shared reads complete -> overlay

        float2 (*sWe)[32] = (float2(*)[32])smem;
        float2 (*sH1)[32] = (float2(*)[32])(smem + 16384);
        float  (*sH2)[20] = (float(*)[20])(smem + 32768);
        float* sbe  = (float*)(smem + 32768 + 5120);
        float* shb1 = sbe + 64;
        float* shb2 = shb1 + 64;
        for (int idx = tid; idx < 64 * 32; idx += 256) {
            int k = idx >> 5, j = idx & 31;
            sWe[k][j] = make_float2(We[k * 64 + j], We[k * 64 + j + 32]);
            sH1[k][j] = make_float2(Hw1[k * 64 + j], Hw1[k * 64 + j + 32]);
        }
        for (int idx = tid; idx < 64 * 20; idx += 256) sH2[idx / 20][idx % 20] = Hw2[idx];
        if (tid < 64) { sbe[tid] = be[tid]; shb1[tid] = hb1[tid]; }
        if (tid >= 64 && tid < 84) shb2[tid - 64] = hb2[tid - 64];
        __syncthreads();

        if (act) {
            float e0 = sbe[lane], e1 = sbe[lane + 32];
#pragma unroll
            for (int k = 0; k < 64; k++) {
                float v = (k < 32) ? __shfl_sync(0xffffffffu, h0, k)
                                   : __shfl_sync(0xffffffffu, h1, k - 32);
                float2 w = sWe[k][lane];
                e0 += v * w.x;
                e1 += v * w.y;
            }
            float t0 = shb1[lane], t1 = shb1[lane + 32];
#pragma unroll
            for (int k = 0; k < 64; k++) {
                float v = (k < 32) ? __shfl_sync(0xffffffffu, e0, k)
                                   : __shfl_sync(0xffffffffu, e1, k - 32);
                float2 w = sH1[k][lane];
                t0 += v * w.x;
                t1 += v * w.y;
            }
            t0 = fmaxf(t0, 0.f);
            t1 = fmaxf(t1, 0.f);
            int jo = (lane < 20) ? lane : 0;
            float o = (lane < 20) ? shb2[lane] : 0.f;
#pragma unroll
            for (int k = 0; k < 64; k++) {
                float v = (k < 32) ? __shfl_sync(0xffffffffu, t0, k)
                                   : __shfl_sync(0xffffffffu, t1, k - 32);
                o += v * sH2[k][jo];
            }
            if (lane < 20) out[i * 20 + lane] = o;
        }
    }
}

extern "C" void kernel_launch(void* const* d_in, const int* in_sizes, int n_in,
                              void* d_out, int out_size) {
    const float* h         = (const float*)d_in[0];
    const float* x         = (const float*)d_in[1];
    const int*   edges     = (const int*)d_in[2];
    const float* emb_in_w  = (const float*)d_in[3];
    const float* emb_in_b  = (const float*)d_in[4];
    const float* emb_out_w = (const float*)d_in[5];
    const float* emb_out_b = (const float*)d_in[6];
    const float* edge_w1   = (const float*)d_in[7];
    const float* edge_b1   = (const float*)d_in[8];
    const float* edge_w2   = (const float*)d_in[9];
    const float* edge_b2   = (const float*)d_in[10];
    const float* node_w1   = (const float*)d_in[11];
    const float* node_b1   = (const float*)d_in[12];
    const float* node_w2   = (const float*)d_in[13];
    const float* node_b2   = (const float*)d_in[14];
    const float* coord_w1  = (const float*)d_in[15];
    const float* coord_b1  = (const float*)d_in[16];
    const float* coord_w2  = (const float*)d_in[17];
    const float* head_w1   = (const float*)d_in[18];
    const float* head_b1   = (const float*)d_in[19];
    const float* head_w2   = (const float*)d_in[20];
    const float* head_b2   = (const float*)d_in[21];
    float* out = (float*)d_out;

    int n = in_sizes[0] / 21;
    int E = in_sizes[2] / 2;
    const int* row = edges;
    const int* col = edges + E;

    int nb  = (n + 255) / 256;
    int nwb = (n + 7) / 8;              // warp-per-node blocks (8 warps/block)
    int nChunks = (E + EW - 1) / EW;    // warp-chunks of EW edges
    int egrid = 592;                    // 148 SMs * 4 CTAs (smem-bound)
    if (egrid * 8 > nChunks) egrid = (nChunks + 7) / 8;

    k_init<<<nb, 256>>>(x, n);
    k_cnt<<<(E + 255) / 256, 256>>>(row, E);
    k_embed<<<nwb, 256>>>(h, emb_in_w, emb_in_b, n);
    k_node_pre<<<nwb, 256>>>(edge_w1, edge_b1, n);   // layer 0 Pa/Pb

    for (int l = 0; l < 4; l++) {
        k_edge<<<egrid, 256>>>(row, col,
                               edge_w1 + l * 129 * 64 + 128 * 64,
                               edge_w2 + l * 4096, edge_b2 + l * 64,
                               coord_w1 + l * 4096, coord_b1 + l * 64,
                               coord_w2 + l * 64, E, nChunks);
        if (l < 3) {
            k_node_fused<<<nwb, 256>>>(node_w1 + l * 128 * 64, node_b1 + l * 64,
                                       node_w2 + l * 4096, node_b2 + l * 64,
                                       edge_w1 + (l + 1) * 129 * 64,
                                       edge_b1 + (l + 1) * 64, n);
        } else {
            k_node_last<<<nwb, 256>>>(node_w1 + l * 128 * 64, node_b1 + l * 64,
                                      node_w2 + l * 4096, node_b2 + l * 64,
                                      emb_out_w, emb_out_b,
                                      head_w1, head_b1, head_w2, head_b2,
                                      out, n);
        }
    }
}